// round 1
// baseline (speedup 1.0000x reference)
#include <cuda_runtime.h>
#include <cuda_bf16.h>
#include <math.h>

#define N_NODES   100000
#define N_EDGES   200000
#define EMB       300
#define EMB2      600
#define NUM_LAYER 5
#define NUM_GRAPHS 5000
#define BN_EPS    1e-5f

// ---------------- device scratch (allocation-free) ----------------
__device__ __align__(16) float g_h[N_NODES * EMB];     // current node features
__device__ __align__(16) float g_agg[N_NODES * EMB];   // aggregation / h2 output
__device__ __align__(16) float g_t[N_NODES * EMB2];    // hidden of GIN MLP
__device__ __align__(16) float g_tab[9 * EMB];         // eemb lookup table (3x3 attr combos)
__device__ float g_stats[2 * EMB];                     // [0:EMB) sum, [EMB:2EMB) centered sumsq
__device__ float g_counts[NUM_GRAPHS];

// ---------------- h0 = x_emb1[x0] + x_emb2[x1] ----------------
__global__ void init_h_kernel(const int* __restrict__ x,
                              const float* __restrict__ e1,
                              const float* __restrict__ e2) {
    int idx = blockIdx.x * blockDim.x + threadIdx.x;
    if (idx >= N_NODES * EMB) return;
    int i = idx / EMB, c = idx - i * EMB;
    int a = x[2 * i], b = x[2 * i + 1];
    g_h[idx] = e1[a * EMB + c] + e2[b * EMB + c];
}

// ---------------- per-layer eemb table + zero BN stats ----------------
__global__ void build_tab_kernel(const float* __restrict__ e1,
                                 const float* __restrict__ e2, int l) {
    int idx = blockIdx.x * blockDim.x + threadIdx.x;
    if (idx < 2 * EMB) g_stats[idx] = 0.f;
    if (idx >= 9 * EMB) return;
    int t = idx / EMB, c = idx - t * EMB;
    int a = t / 3, b = t - a * 3;
    g_tab[idx] = e1[(l * 6 + a) * EMB + c] + e2[(l * 3 + b) * EMB + c];
}

// ---------------- agg = h + tab[0]  (self-loop message) ----------------
__global__ void init_agg_kernel() {
    int idx = blockIdx.x * blockDim.x + threadIdx.x;
    if (idx >= N_NODES * EMB) return;
    g_agg[idx] = g_h[idx] + g_tab[idx % EMB];
}

// ---------------- edge scatter: agg[dst] += h[src] + tab[attr] ----------------
__global__ __launch_bounds__(256) void scatter_edges_kernel(
        const int* __restrict__ ei, const int* __restrict__ ea) {
    int e = blockIdx.x * 8 + (threadIdx.x >> 5);
    if (e >= N_EDGES) return;
    int lane = threadIdx.x & 31;
    int src = ei[e];
    int dst = ei[N_EDGES + e];
    int t = ea[2 * e] * 3 + ea[2 * e + 1];
    const float4* hs = (const float4*)(g_h + (size_t)src * EMB);
    const float4* tb = (const float4*)(g_tab + t * EMB);
    float* ag = g_agg + (size_t)dst * EMB;
    #pragma unroll
    for (int i = lane; i < EMB / 4; i += 32) {
        float4 hv = hs[i];
        float4 tv = tb[i];
        atomicAdd(&ag[4 * i + 0], hv.x + tv.x);
        atomicAdd(&ag[4 * i + 1], hv.y + tv.y);
        atomicAdd(&ag[4 * i + 2], hv.z + tv.z);
        atomicAdd(&ag[4 * i + 3], hv.w + tv.w);
    }
}

// ---------------- tiled SGEMM: C = act(A@B + bias) ----------------
#define GBM 128
#define GBN 128
#define GBK 8
#define GTM 8
#define GTN 8
__global__ __launch_bounds__(256) void sgemm_bias_act_kernel(
        const float* __restrict__ A, const float* __restrict__ B,
        const float* __restrict__ bias, float* __restrict__ C,
        int M, int N, int K, int doRelu) {
    __shared__ float As[GBK][GBM];
    __shared__ float Bs[GBK][GBN];
    const int tid = threadIdx.x;
    const int row0 = blockIdx.y * GBM;
    const int col0 = blockIdx.x * GBN;
    const int trow = (tid / 16) * GTM;
    const int tcol = (tid % 16) * GTN;
    float acc[GTM][GTN] = {};

    for (int kt = 0; kt < K; kt += GBK) {
        #pragma unroll
        for (int it = 0; it < (GBM * GBK) / 256; ++it) {
            int idx = tid + it * 256;
            int r = idx >> 3, k = idx & 7;
            int gr = row0 + r, gk = kt + k;
            As[k][r] = (gr < M && gk < K) ? A[(size_t)gr * K + gk] : 0.f;
        }
        #pragma unroll
        for (int it = 0; it < (GBK * GBN) / 256; ++it) {
            int idx = tid + it * 256;
            int k = idx >> 7, c = idx & 127;
            int gk = kt + k, gc = col0 + c;
            Bs[k][c] = (gk < K && gc < N) ? B[(size_t)gk * N + gc] : 0.f;
        }
        __syncthreads();
        #pragma unroll
        for (int k = 0; k < GBK; ++k) {
            float a[GTM], b[GTN];
            *(float4*)&a[0] = *(const float4*)&As[k][trow];
            *(float4*)&a[4] = *(const float4*)&As[k][trow + 4];
            *(float4*)&b[0] = *(const float4*)&Bs[k][tcol];
            *(float4*)&b[4] = *(const float4*)&Bs[k][tcol + 4];
            #pragma unroll
            for (int i = 0; i < GTM; ++i)
                #pragma unroll
                for (int j = 0; j < GTN; ++j)
                    acc[i][j] += a[i] * b[j];
        }
        __syncthreads();
    }
    #pragma unroll
    for (int i = 0; i < GTM; ++i) {
        int gr = row0 + trow + i;
        if (gr >= M) continue;
        #pragma unroll
        for (int j = 0; j < GTN; ++j) {
            int gc = col0 + tcol + j;
            if (gc >= N) continue;
            float v = acc[i][j] + bias[gc];
            if (doRelu) v = fmaxf(v, 0.f);
            C[(size_t)gr * N + gc] = v;
        }
    }
}

// ---------------- BN pass 1: per-channel sum ----------------
#define BNROWS 256
__global__ void bn_sum_kernel(const float* __restrict__ X) {
    int c = threadIdx.x;
    if (c >= EMB) return;
    int r0 = blockIdx.x * BNROWS;
    int r1 = min(r0 + BNROWS, N_NODES);
    float s = 0.f;
    for (int r = r0; r < r1; ++r) s += X[(size_t)r * EMB + c];
    atomicAdd(&g_stats[c], s);
}

// ---------------- BN pass 2: per-channel centered sumsq ----------------
__global__ void bn_sumsq_kernel(const float* __restrict__ X) {
    int c = threadIdx.x;
    if (c >= EMB) return;
    float mu = g_stats[c] * (1.f / N_NODES);
    int r0 = blockIdx.x * BNROWS;
    int r1 = min(r0 + BNROWS, N_NODES);
    float s = 0.f;
    for (int r = r0; r < r1; ++r) {
        float d = X[(size_t)r * EMB + c] - mu;
        s += d * d;
    }
    atomicAdd(&g_stats[EMB + c], s);
}

// ---------------- BN apply (+optional relu), write g_h ----------------
__global__ void bn_apply_kernel(const float* __restrict__ X,
                                const float* __restrict__ gamma,
                                const float* __restrict__ beta,
                                int l, int doRelu) {
    int idx = blockIdx.x * blockDim.x + threadIdx.x;
    if (idx >= N_NODES * EMB) return;
    int c = idx % EMB;
    float mu = g_stats[c] * (1.f / N_NODES);
    float var = g_stats[EMB + c] * (1.f / N_NODES);
    float sc = rsqrtf(var + BN_EPS) * gamma[l * EMB + c];
    float v = (X[idx] - mu) * sc + beta[l * EMB + c];
    g_h[idx] = doRelu ? fmaxf(v, 0.f) : v;
}

// ---------------- pooling ----------------
__global__ void pool_zero_kernel(float* __restrict__ out) {
    int idx = blockIdx.x * blockDim.x + threadIdx.x;
    if (idx < NUM_GRAPHS) g_counts[idx] = 0.f;
    if (idx < NUM_GRAPHS * EMB) out[idx] = 0.f;
}

__global__ void pool_count_kernel(const int* __restrict__ batch) {
    int i = blockIdx.x * blockDim.x + threadIdx.x;
    if (i >= N_NODES) return;
    atomicAdd(&g_counts[batch[i]], 1.f);
}

__global__ void pool_scatter_kernel(const int* __restrict__ batch,
                                    float* __restrict__ out) {
    int idx = blockIdx.x * blockDim.x + threadIdx.x;
    if (idx >= N_NODES * EMB) return;
    int i = idx / EMB, c = idx - i * EMB;
    int b = batch[i];
    atomicAdd(&out[(size_t)b * EMB + c], g_h[idx]);
}

__global__ void pool_div_kernel(float* __restrict__ out) {
    int idx = blockIdx.x * blockDim.x + threadIdx.x;
    if (idx >= NUM_GRAPHS * EMB) return;
    out[idx] /= fmaxf(g_counts[idx / EMB], 1.f);
}

// ---------------- launch ----------------
extern "C" void kernel_launch(void* const* d_in, const int* in_sizes, int n_in,
                              void* d_out, int out_size) {
    const int*   x        = (const int*)d_in[0];
    const int*   edge_idx = (const int*)d_in[1];
    const int*   edge_att = (const int*)d_in[2];
    const int*   batch    = (const int*)d_in[3];
    const float* x_emb1   = (const float*)d_in[4];
    const float* x_emb2   = (const float*)d_in[5];
    const float* edge_e1  = (const float*)d_in[6];
    const float* edge_e2  = (const float*)d_in[7];
    const float* W1       = (const float*)d_in[8];
    const float* b1       = (const float*)d_in[9];
    const float* W2       = (const float*)d_in[10];
    const float* b2       = (const float*)d_in[11];
    const float* gamma    = (const float*)d_in[12];
    const float* beta     = (const float*)d_in[13];
    float* out = (float*)d_out;

    const int NE = N_NODES * EMB;           // 30,000,000
    const int TPB = 256;

    init_h_kernel<<<(NE + TPB - 1) / TPB, TPB>>>(x, x_emb1, x_emb2);

    // resolve device symbol addresses (host pointers to device globals)
    float *p_h, *p_agg, *p_t;
    cudaGetSymbolAddress((void**)&p_h, g_h);
    cudaGetSymbolAddress((void**)&p_agg, g_agg);
    cudaGetSymbolAddress((void**)&p_t, g_t);

    dim3 g1((EMB2 + GBN - 1) / GBN, (N_NODES + GBM - 1) / GBM);  // GEMM1 grid
    dim3 g2((EMB + GBN - 1) / GBN, (N_NODES + GBM - 1) / GBM);   // GEMM2 grid
    int bn_grid = (N_NODES + BNROWS - 1) / BNROWS;

    for (int l = 0; l < NUM_LAYER; ++l) {
        build_tab_kernel<<<(9 * EMB + TPB - 1) / TPB, TPB>>>(edge_e1, edge_e2, l);
        init_agg_kernel<<<(NE + TPB - 1) / TPB, TPB>>>();
        scatter_edges_kernel<<<(N_EDGES + 7) / 8, 256>>>(edge_idx, edge_att);
        // t = relu(agg @ W1[l] + b1[l])   [N, 600]
        sgemm_bias_act_kernel<<<g1, 256>>>(p_agg, W1 + (size_t)l * EMB * EMB2,
                                           b1 + l * EMB2, p_t,
                                           N_NODES, EMB2, EMB, 1);
        // h2 = t @ W2[l] + b2[l]          [N, 300]  (written into g_agg)
        sgemm_bias_act_kernel<<<g2, 256>>>(p_t, W2 + (size_t)l * EMB2 * EMB,
                                           b2 + l * EMB, p_agg,
                                           N_NODES, EMB, EMB2, 0);
        bn_sum_kernel<<<bn_grid, 320>>>(p_agg);
        bn_sumsq_kernel<<<bn_grid, 320>>>(p_agg);
        bn_apply_kernel<<<(NE + TPB - 1) / TPB, TPB>>>(p_agg, gamma, beta, l,
                                                        (l == NUM_LAYER - 1) ? 0 : 1);
    }

    pool_zero_kernel<<<(NUM_GRAPHS * EMB + TPB - 1) / TPB, TPB>>>(out);
    pool_count_kernel<<<(N_NODES + TPB - 1) / TPB, TPB>>>(batch);
    pool_scatter_kernel<<<(NE + TPB - 1) / TPB, TPB>>>(batch, out);
    pool_div_kernel<<<(NUM_GRAPHS * EMB + TPB - 1) / TPB, TPB>>>(out);
}

// round 3
// speedup vs baseline: 2.0397x; 2.0397x over previous
#include <cuda_runtime.h>
#include <cuda_bf16.h>
#include <math.h>
#include <stdint.h>

#define N_NODES   100000
#define N_EDGES   200000
#define EMB       300
#define EMB2      600
#define NUM_LAYER 5
#define NUM_GRAPHS 5000
#define BN_EPS    1e-5f

// ---------------- device scratch (allocation-free) ----------------
__device__ __align__(16) float g_h[N_NODES * EMB];     // current node features
__device__ __align__(16) float g_agg[N_NODES * EMB];   // aggregation / h2 output
__device__ __align__(16) float g_t[N_NODES * EMB2];    // hidden of GIN MLP
__device__ __align__(16) float g_tab[9 * EMB];         // eemb lookup table (3x3 attr combos)
__device__ float g_stats[2 * EMB];                     // [0:EMB) sum, [EMB:2EMB) centered sumsq
__device__ float g_counts[NUM_GRAPHS];

// ---------------- h0 = x_emb1[x0] + x_emb2[x1] ----------------
__global__ void init_h_kernel(const int* __restrict__ x,
                              const float* __restrict__ e1,
                              const float* __restrict__ e2) {
    int idx = blockIdx.x * blockDim.x + threadIdx.x;
    if (idx >= N_NODES * EMB) return;
    int i = idx / EMB, c = idx - i * EMB;
    int a = x[2 * i], b = x[2 * i + 1];
    g_h[idx] = e1[a * EMB + c] + e2[b * EMB + c];
}

// ---------------- per-layer eemb table + zero BN stats ----------------
__global__ void build_tab_kernel(const float* __restrict__ e1,
                                 const float* __restrict__ e2, int l) {
    int idx = blockIdx.x * blockDim.x + threadIdx.x;
    if (idx < 2 * EMB) g_stats[idx] = 0.f;
    if (idx >= 9 * EMB) return;
    int t = idx / EMB, c = idx - t * EMB;
    int a = t / 3, b = t - a * 3;
    g_tab[idx] = e1[(l * 6 + a) * EMB + c] + e2[(l * 3 + b) * EMB + c];
}

// ---------------- agg = h + tab[0]  (self-loop message) ----------------
__global__ void init_agg_kernel() {
    int idx = blockIdx.x * blockDim.x + threadIdx.x;
    if (idx >= N_NODES * EMB) return;
    g_agg[idx] = g_h[idx] + g_tab[idx % EMB];
}

// ---------------- edge scatter: agg[dst] += h[src] + tab[attr] ----------------
__global__ __launch_bounds__(256) void scatter_edges_kernel(
        const int* __restrict__ ei, const int* __restrict__ ea) {
    int e = blockIdx.x * 8 + (threadIdx.x >> 5);
    if (e >= N_EDGES) return;
    int lane = threadIdx.x & 31;
    int src = ei[e];
    int dst = ei[N_EDGES + e];
    int t = ea[2 * e] * 3 + ea[2 * e + 1];
    const float4* hs = (const float4*)(g_h + (size_t)src * EMB);
    const float4* tb = (const float4*)(g_tab + t * EMB);
    float* ag = g_agg + (size_t)dst * EMB;
    #pragma unroll
    for (int i = lane; i < EMB / 4; i += 32) {
        float4 hv = hs[i];
        float4 tv = tb[i];
        atomicAdd(&ag[4 * i + 0], hv.x + tv.x);
        atomicAdd(&ag[4 * i + 1], hv.y + tv.y);
        atomicAdd(&ag[4 * i + 2], hv.z + tv.z);
        atomicAdd(&ag[4 * i + 3], hv.w + tv.w);
    }
}

// ============ 3xTF32 tensor-core GEMM: C = act(A@B + bias) ============
// Block tile 128x128, K-tile 32, 8 warps x (64x32) via m16n8k8.
// Each operand split hi/lo; D = Ah*Bh + Al*Bh + Ah*Bl (fp32 accumulate).
#define KT 32
#define ASTRIDE 36    // conflict-free: bank(m*36+k) -> 4g+t bijective
#define BSTRIDE 132   // conflict-free: bank(k*132+n) -> 4t+g bijective
#define A_WORDS (128 * ASTRIDE)
#define B_WORDS (KT * BSTRIDE)
#define SMEM_BYTES ((2 * A_WORDS + 2 * B_WORDS) * 4)

__device__ __forceinline__ uint32_t f2tf(float f) {
    uint32_t u;
    asm volatile("cvt.rna.tf32.f32 %0, %1;" : "=r"(u) : "f"(f));
    return u;
}

__device__ __forceinline__ void mma8(float* c, const uint32_t* a, const uint32_t* b) {
    asm volatile(
        "mma.sync.aligned.m16n8k8.row.col.f32.tf32.tf32.f32 "
        "{%0,%1,%2,%3},{%4,%5,%6,%7},{%8,%9},{%0,%1,%2,%3};\n"
        : "+f"(c[0]), "+f"(c[1]), "+f"(c[2]), "+f"(c[3])
        : "r"(a[0]), "r"(a[1]), "r"(a[2]), "r"(a[3]), "r"(b[0]), "r"(b[1]));
}

__device__ __forceinline__ void split4(float4 f, uint4& hi, uint4& lo) {
    hi = make_uint4(f2tf(f.x), f2tf(f.y), f2tf(f.z), f2tf(f.w));
    lo = make_uint4(f2tf(f.x - __uint_as_float(hi.x)),
                    f2tf(f.y - __uint_as_float(hi.y)),
                    f2tf(f.z - __uint_as_float(hi.z)),
                    f2tf(f.w - __uint_as_float(hi.w)));
}

__global__ __launch_bounds__(256) void gemm_3xtf32_kernel(
        const float* __restrict__ A, const float* __restrict__ B,
        const float* __restrict__ bias, float* __restrict__ C,
        int M, int N, int K, int doRelu) {
    extern __shared__ uint32_t sm[];
    uint32_t* Ah = sm;
    uint32_t* Al = Ah + A_WORDS;
    uint32_t* Bh = Al + A_WORDS;
    uint32_t* Bl = Bh + B_WORDS;

    const int tid  = threadIdx.x;
    const int lane = tid & 31;
    const int warp = tid >> 5;
    const int g = lane >> 2;          // 0..7
    const int t = lane & 3;           // 0..3
    const int wm = (warp & 1) * 64;
    const int wn = (warp >> 1) * 32;
    const int row0 = blockIdx.y * 128;
    const int col0 = blockIdx.x * 128;

    float c[4][4][4] = {};
    float4 ra[4], rb[4];

    const int nk = (K + KT - 1) / KT;

    // --- prefetch tile 0 into registers ---
    #pragma unroll
    for (int it = 0; it < 4; ++it) {
        int idx = tid + it * 256;
        {
            int r = idx >> 3, k4 = idx & 7;
            int gr = row0 + r, gk = k4 * 4;
            ra[it] = (gr < M && gk < K) ? *(const float4*)(A + (size_t)gr * K + gk)
                                        : make_float4(0.f, 0.f, 0.f, 0.f);
        }
        {
            int k = idx >> 5, n4 = idx & 31;
            int gn = col0 + n4 * 4;
            rb[it] = (k < K && gn < N) ? *(const float4*)(B + (size_t)k * N + gn)
                                       : make_float4(0.f, 0.f, 0.f, 0.f);
        }
    }

    for (int kt = 0; kt < nk; ++kt) {
        // --- split & store staged tile to smem ---
        #pragma unroll
        for (int it = 0; it < 4; ++it) {
            int idx = tid + it * 256;
            {
                int r = idx >> 3, k4 = idx & 7;
                uint4 hi, lo;
                split4(ra[it], hi, lo);
                *(uint4*)&Ah[r * ASTRIDE + k4 * 4] = hi;
                *(uint4*)&Al[r * ASTRIDE + k4 * 4] = lo;
            }
            {
                int k = idx >> 5, n4 = idx & 31;
                uint4 hi, lo;
                split4(rb[it], hi, lo);
                *(uint4*)&Bh[k * BSTRIDE + n4 * 4] = hi;
                *(uint4*)&Bl[k * BSTRIDE + n4 * 4] = lo;
            }
        }
        __syncthreads();

        // --- prefetch next tile ---
        if (kt + 1 < nk) {
            int k0 = (kt + 1) * KT;
            #pragma unroll
            for (int it = 0; it < 4; ++it) {
                int idx = tid + it * 256;
                {
                    int r = idx >> 3, k4 = idx & 7;
                    int gr = row0 + r, gk = k0 + k4 * 4;
                    ra[it] = (gr < M && gk < K) ? *(const float4*)(A + (size_t)gr * K + gk)
                                                : make_float4(0.f, 0.f, 0.f, 0.f);
                }
                {
                    int k = idx >> 5, n4 = idx & 31;
                    int gk = k0 + k, gn = col0 + n4 * 4;
                    rb[it] = (gk < K && gn < N) ? *(const float4*)(B + (size_t)gk * N + gn)
                                                : make_float4(0.f, 0.f, 0.f, 0.f);
                }
            }
        }

        // --- compute: 4 k8-steps, 3x16 MMAs each ---
        #pragma unroll
        for (int ks = 0; ks < KT / 8; ++ks) {
            int kk = ks * 8;
            uint32_t afh[4][4], afl[4][4], bfh[4][2], bfl[4][2];
            #pragma unroll
            for (int i = 0; i < 4; ++i) {
                int m = wm + i * 16 + g;
                int o0 = m * ASTRIDE + kk + t;
                int o1 = (m + 8) * ASTRIDE + kk + t;
                afh[i][0] = Ah[o0];     afh[i][1] = Ah[o1];
                afh[i][2] = Ah[o0 + 4]; afh[i][3] = Ah[o1 + 4];
                afl[i][0] = Al[o0];     afl[i][1] = Al[o1];
                afl[i][2] = Al[o0 + 4]; afl[i][3] = Al[o1 + 4];
            }
            #pragma unroll
            for (int j = 0; j < 4; ++j) {
                int n = wn + j * 8 + g;
                int o0 = (kk + t) * BSTRIDE + n;
                int o1 = (kk + t + 4) * BSTRIDE + n;
                bfh[j][0] = Bh[o0]; bfh[j][1] = Bh[o1];
                bfl[j][0] = Bl[o0]; bfl[j][1] = Bl[o1];
            }
            #pragma unroll
            for (int i = 0; i < 4; ++i)
                #pragma unroll
                for (int j = 0; j < 4; ++j) {
                    mma8(c[i][j], afl[i], bfh[j]);   // small terms first
                    mma8(c[i][j], afh[i], bfl[j]);
                    mma8(c[i][j], afh[i], bfh[j]);
                }
        }
        __syncthreads();
    }

    // --- epilogue: bias + optional relu, float2 stores ---
    #pragma unroll
    for (int i = 0; i < 4; ++i) {
        int r = row0 + wm + i * 16 + g;
        #pragma unroll
        for (int j = 0; j < 4; ++j) {
            int cc = col0 + wn + j * 8 + 2 * t;
            if (cc >= N) continue;
            float bx = bias[cc], by = bias[cc + 1];
            if (r < M) {
                float2 v = make_float2(c[i][j][0] + bx, c[i][j][1] + by);
                if (doRelu) { v.x = fmaxf(v.x, 0.f); v.y = fmaxf(v.y, 0.f); }
                *(float2*)&C[(size_t)r * N + cc] = v;
            }
            int r2 = r + 8;
            if (r2 < M) {
                float2 v = make_float2(c[i][j][2] + bx, c[i][j][3] + by);
                if (doRelu) { v.x = fmaxf(v.x, 0.f); v.y = fmaxf(v.y, 0.f); }
                *(float2*)&C[(size_t)r2 * N + cc] = v;
            }
        }
    }
}

// ---------------- BN pass 1: per-channel sum ----------------
#define BNROWS 256
__global__ void bn_sum_kernel(const float* __restrict__ X) {
    int c = threadIdx.x;
    if (c >= EMB) return;
    int r0 = blockIdx.x * BNROWS;
    int r1 = min(r0 + BNROWS, N_NODES);
    float s = 0.f;
    for (int r = r0; r < r1; ++r) s += X[(size_t)r * EMB + c];
    atomicAdd(&g_stats[c], s);
}

// ---------------- BN pass 2: per-channel centered sumsq ----------------
__global__ void bn_sumsq_kernel(const float* __restrict__ X) {
    int c = threadIdx.x;
    if (c >= EMB) return;
    float mu = g_stats[c] * (1.f / N_NODES);
    int r0 = blockIdx.x * BNROWS;
    int r1 = min(r0 + BNROWS, N_NODES);
    float s = 0.f;
    for (int r = r0; r < r1; ++r) {
        float d = X[(size_t)r * EMB + c] - mu;
        s += d * d;
    }
    atomicAdd(&g_stats[EMB + c], s);
}

// ---------------- BN apply (+optional relu), write g_h ----------------
__global__ void bn_apply_kernel(const float* __restrict__ X,
                                const float* __restrict__ gamma,
                                const float* __restrict__ beta,
                                int l, int doRelu) {
    int idx = blockIdx.x * blockDim.x + threadIdx.x;
    if (idx >= N_NODES * EMB) return;
    int c = idx % EMB;
    float mu = g_stats[c] * (1.f / N_NODES);
    float var = g_stats[EMB + c] * (1.f / N_NODES);
    float sc = rsqrtf(var + BN_EPS) * gamma[l * EMB + c];
    float v = (X[idx] - mu) * sc + beta[l * EMB + c];
    g_h[idx] = doRelu ? fmaxf(v, 0.f) : v;
}

// ---------------- pooling ----------------
__global__ void pool_zero_kernel(float* __restrict__ out) {
    int idx = blockIdx.x * blockDim.x + threadIdx.x;
    if (idx < NUM_GRAPHS) g_counts[idx] = 0.f;
    if (idx < NUM_GRAPHS * EMB) out[idx] = 0.f;
}

__global__ void pool_count_kernel(const int* __restrict__ batch) {
    int i = blockIdx.x * blockDim.x + threadIdx.x;
    if (i >= N_NODES) return;
    atomicAdd(&g_counts[batch[i]], 1.f);
}

__global__ void pool_scatter_kernel(const int* __restrict__ batch,
                                    float* __restrict__ out) {
    int idx = blockIdx.x * blockDim.x + threadIdx.x;
    if (idx >= N_NODES * EMB) return;
    int i = idx / EMB, c = idx - i * EMB;
    int b = batch[i];
    atomicAdd(&out[(size_t)b * EMB + c], g_h[idx]);
}

__global__ void pool_div_kernel(float* __restrict__ out) {
    int idx = blockIdx.x * blockDim.x + threadIdx.x;
    if (idx >= NUM_GRAPHS * EMB) return;
    out[idx] /= fmaxf(g_counts[idx / EMB], 1.f);
}

// ---------------- launch ----------------
extern "C" void kernel_launch(void* const* d_in, const int* in_sizes, int n_in,
                              void* d_out, int out_size) {
    const int*   x        = (const int*)d_in[0];
    const int*   edge_idx = (const int*)d_in[1];
    const int*   edge_att = (const int*)d_in[2];
    const int*   batch    = (const int*)d_in[3];
    const float* x_emb1   = (const float*)d_in[4];
    const float* x_emb2   = (const float*)d_in[5];
    const float* edge_e1  = (const float*)d_in[6];
    const float* edge_e2  = (const float*)d_in[7];
    const float* W1       = (const float*)d_in[8];
    const float* b1       = (const float*)d_in[9];
    const float* W2       = (const float*)d_in[10];
    const float* b2       = (const float*)d_in[11];
    const float* gamma    = (const float*)d_in[12];
    const float* beta     = (const float*)d_in[13];
    float* out = (float*)d_out;

    const int NE = N_NODES * EMB;
    const int TPB = 256;

    static int configured = 0;
    if (!configured) {
        cudaFuncSetAttribute(gemm_3xtf32_kernel,
                             cudaFuncAttributeMaxDynamicSharedMemorySize, SMEM_BYTES);
        configured = 1;
    }

    init_h_kernel<<<(NE + TPB - 1) / TPB, TPB>>>(x, x_emb1, x_emb2);

    float *p_h, *p_agg, *p_t;
    cudaGetSymbolAddress((void**)&p_h, g_h);
    cudaGetSymbolAddress((void**)&p_agg, g_agg);
    cudaGetSymbolAddress((void**)&p_t, g_t);

    dim3 g1((EMB2 + 127) / 128, (N_NODES + 127) / 128);
    dim3 g2((EMB  + 127) / 128, (N_NODES + 127) / 128);
    int bn_grid = (N_NODES + BNROWS - 1) / BNROWS;

    for (int l = 0; l < NUM_LAYER; ++l) {
        build_tab_kernel<<<(9 * EMB + TPB - 1) / TPB, TPB>>>(edge_e1, edge_e2, l);
        init_agg_kernel<<<(NE + TPB - 1) / TPB, TPB>>>();
        scatter_edges_kernel<<<(N_EDGES + 7) / 8, 256>>>(edge_idx, edge_att);
        // t = relu(agg @ W1[l] + b1[l])   [N, 600]
        gemm_3xtf32_kernel<<<g1, 256, SMEM_BYTES>>>(p_agg, W1 + (size_t)l * EMB * EMB2,
                                                    b1 + l * EMB2, p_t,
                                                    N_NODES, EMB2, EMB, 1);
        // h2 = t @ W2[l] + b2[l]          [N, 300]
        gemm_3xtf32_kernel<<<g2, 256, SMEM_BYTES>>>(p_t, W2 + (size_t)l * EMB2 * EMB,
                                                    b2 + l * EMB, p_agg,
                                                    N_NODES, EMB, EMB2, 0);
        bn_sum_kernel<<<bn_grid, 320>>>(p_agg);
        bn_sumsq_kernel<<<bn_grid, 320>>>(p_agg);
        bn_apply_kernel<<<(NE + TPB - 1) / TPB, TPB>>>(p_agg, gamma, beta, l,
                                                        (l == NUM_LAYER - 1) ? 0 : 1);
    }

    pool_zero_kernel<<<(NUM_GRAPHS * EMB + TPB - 1) / TPB, TPB>>>(out);
    pool_count_kernel<<<(N_NODES + TPB - 1) / TPB, TPB>>>(batch);
    pool_scatter_kernel<<<(NE + TPB - 1) / TPB, TPB>>>(batch, out);
    pool_div_kernel<<<(NUM_GRAPHS * EMB + TPB - 1) / TPB, TPB>>>(out);
}

// round 5
// speedup vs baseline: 2.6997x; 1.3236x over previous
#include <cuda_runtime.h>
#include <cuda_bf16.h>
#include <math.h>
#include <stdint.h>

#define N_NODES   100000
#define N_EDGES   200000
#define EMB       300
#define EMB2      600
#define NUM_LAYER 5
#define NUM_GRAPHS 5000
#define BN_EPS    1e-5f

// ---------------- device scratch (allocation-free) ----------------
__device__ __align__(16) float g_h[N_NODES * EMB];
__device__ __align__(16) float g_agg[N_NODES * EMB];
__device__ __align__(16) float g_t[N_NODES * EMB2];
__device__ __align__(16) float g_tab[9 * EMB];
__device__ float g_stats[2 * EMB];
__device__ float g_counts[NUM_GRAPHS];
// transposed + split weights (bf16 hi/lo), zero-padded: max 384x640 = 245760
__device__ __align__(16) __nv_bfloat16 g_wth[245760];
__device__ __align__(16) __nv_bfloat16 g_wtl[245760];

// ---------------- h0 = x_emb1[x0] + x_emb2[x1] ----------------
__global__ void init_h_kernel(const int* __restrict__ x,
                              const float* __restrict__ e1,
                              const float* __restrict__ e2) {
    int idx = blockIdx.x * blockDim.x + threadIdx.x;
    if (idx >= N_NODES * EMB) return;
    int i = idx / EMB, c = idx - i * EMB;
    int a = x[2 * i], b = x[2 * i + 1];
    g_h[idx] = e1[a * EMB + c] + e2[b * EMB + c];
}

// ---------------- per-layer eemb table + zero BN stats ----------------
__global__ void build_tab_kernel(const float* __restrict__ e1,
                                 const float* __restrict__ e2, int l) {
    int idx = blockIdx.x * blockDim.x + threadIdx.x;
    if (idx < 2 * EMB) g_stats[idx] = 0.f;
    if (idx >= 9 * EMB) return;
    int t = idx / EMB, c = idx - t * EMB;
    int a = t / 3, b = t - a * 3;
    g_tab[idx] = e1[(l * 6 + a) * EMB + c] + e2[(l * 3 + b) * EMB + c];
}

// ---------------- agg = h + tab[0]  (self-loop message) ----------------
__global__ void init_agg_kernel() {
    int idx = blockIdx.x * blockDim.x + threadIdx.x;
    if (idx >= N_NODES * EMB) return;
    g_agg[idx] = g_h[idx] + g_tab[idx % EMB];
}

// ---------------- edge scatter: agg[dst] += h[src] + tab[attr] ----------------
__global__ __launch_bounds__(256) void scatter_edges_kernel(
        const int* __restrict__ ei, const int* __restrict__ ea) {
    int e = blockIdx.x * 8 + (threadIdx.x >> 5);
    if (e >= N_EDGES) return;
    int lane = threadIdx.x & 31;
    int src = ei[e];
    int dst = ei[N_EDGES + e];
    int t = ea[2 * e] * 3 + ea[2 * e + 1];
    const float4* hs = (const float4*)(g_h + (size_t)src * EMB);
    const float4* tb = (const float4*)(g_tab + t * EMB);
    float* ag = g_agg + (size_t)dst * EMB;
    #pragma unroll
    for (int i = lane; i < EMB / 4; i += 32) {
        float4 hv = hs[i];
        float4 tv = tb[i];
        atomicAdd(&ag[4 * i + 0], hv.x + tv.x);
        atomicAdd(&ag[4 * i + 1], hv.y + tv.y);
        atomicAdd(&ag[4 * i + 2], hv.z + tv.z);
        atomicAdd(&ag[4 * i + 3], hv.w + tv.w);
    }
}

// ---------------- weight transpose + bf16 hi/lo split ----------------
// W [K,N] fp32  ->  g_wth/g_wtl [Npad, Kpad] bf16, zero-padded.
__global__ void transpose_split_kernel(const float* __restrict__ W,
                                       int N, int K, int Npad, int Kpad) {
    __shared__ float tile[32][33];
    int tx = threadIdx.x, ty = threadIdx.y;
    int nb = blockIdx.x * 32, kb = blockIdx.y * 32;
    #pragma unroll
    for (int j = 0; j < 4; ++j) {
        int gk = kb + ty + j * 8, gn = nb + tx;
        tile[ty + j * 8][tx] = (gk < K && gn < N) ? W[(size_t)gk * N + gn] : 0.f;
    }
    __syncthreads();
    #pragma unroll
    for (int j = 0; j < 4; ++j) {
        int gn = nb + ty + j * 8, gk = kb + tx;
        if (gn < Npad && gk < Kpad) {
            float v = tile[tx][ty + j * 8];
            __nv_bfloat16 hi = __float2bfloat16(v);
            __nv_bfloat16 lo = __float2bfloat16(v - __bfloat162float(hi));
            g_wth[(size_t)gn * Kpad + gk] = hi;
            g_wtl[(size_t)gn * Kpad + gk] = lo;
        }
    }
}

// ============ 4-term split-bf16 tensor GEMM: C = act(A@W + bias) ============
// Block tile 128x128, K-tile 32, 8 warps x (64x32), mma.m16n8k16.bf16.
// A,B split hi/lo; D = Al*Bl + Al*Bh + Ah*Bl + Ah*Bh (fp32 accumulate).
#define KT 32
#define WSTRIDE 20   // words per row (16 k-pairs + 4 pad): g*20+t conflict-free

__device__ __forceinline__ void mma16(float* c, const uint32_t* a, const uint32_t* b) {
    asm volatile(
        "mma.sync.aligned.m16n8k16.row.col.f32.bf16.bf16.f32 "
        "{%0,%1,%2,%3},{%4,%5,%6,%7},{%8,%9},{%0,%1,%2,%3};\n"
        : "+f"(c[0]), "+f"(c[1]), "+f"(c[2]), "+f"(c[3])
        : "r"(a[0]), "r"(a[1]), "r"(a[2]), "r"(a[3]), "r"(b[0]), "r"(b[1]));
}

__device__ __forceinline__ void split4(float4 f, uint2& hi, uint2& lo) {
    __nv_bfloat16 h0 = __float2bfloat16(f.x), h1 = __float2bfloat16(f.y),
                  h2 = __float2bfloat16(f.z), h3 = __float2bfloat16(f.w);
    __nv_bfloat16 l0 = __float2bfloat16(f.x - __bfloat162float(h0)),
                  l1 = __float2bfloat16(f.y - __bfloat162float(h1)),
                  l2 = __float2bfloat16(f.z - __bfloat162float(h2)),
                  l3 = __float2bfloat16(f.w - __bfloat162float(h3));
    __nv_bfloat162 ha(h0, h1), hb(h2, h3), la(l0, l1), lb(l2, l3);
    hi = make_uint2(*(uint32_t*)&ha, *(uint32_t*)&hb);
    lo = make_uint2(*(uint32_t*)&la, *(uint32_t*)&lb);
}

__global__ __launch_bounds__(256) void gemm_bf16x4_kernel(
        const float* __restrict__ A,
        const __nv_bfloat16* __restrict__ Wh,
        const __nv_bfloat16* __restrict__ Wl,
        const float* __restrict__ bias, float* __restrict__ C,
        int M, int N, int K, int Kpad, int doRelu) {
    __shared__ __align__(16) uint32_t Ah[128 * WSTRIDE];
    __shared__ __align__(16) uint32_t Al[128 * WSTRIDE];
    __shared__ __align__(16) uint32_t Bh[128 * WSTRIDE];
    __shared__ __align__(16) uint32_t Bl[128 * WSTRIDE];

    const int tid  = threadIdx.x;
    const int lane = tid & 31;
    const int warp = tid >> 5;
    const int g = lane >> 2;          // 0..7
    const int t = lane & 3;           // 0..3
    const int wm = (warp & 1) * 64;
    const int wn = (warp >> 1) * 32;
    const int row0 = blockIdx.y * 128;
    const int col0 = blockIdx.x * 128;

    float c[4][4][4] = {};
    float4 ra[4];     // A staging: 128x32 fp32 = 1024 float4
    uint4  rb[4];     // B staging: 2 terms x 512 uint4

    const int nk = (K + KT - 1) / KT;

    // ---- prefetch tile 0 ----
    #pragma unroll
    for (int it = 0; it < 4; ++it) {
        int idx = tid + it * 256;
        {
            int r = idx >> 3, kq = idx & 7;
            int gr = row0 + r, gk = kq * 4;
            ra[it] = (gr < M && gk < K) ? *(const float4*)(A + (size_t)gr * K + gk)
                                        : make_float4(0.f, 0.f, 0.f, 0.f);
        }
        {
            int term = idx >> 9, rem = idx & 511;
            int r = rem >> 2, q = rem & 3;
            rb[it] = *(const uint4*)((term ? Wl : Wh) +
                     (size_t)(col0 + r) * Kpad + q * 8);
        }
    }

    for (int kt = 0; kt < nk; ++kt) {
        // ---- store staged tile to smem ----
        #pragma unroll
        for (int it = 0; it < 4; ++it) {
            int idx = tid + it * 256;
            {
                int r = idx >> 3, kq = idx & 7;
                uint2 hi, lo;
                split4(ra[it], hi, lo);
                *(uint2*)&Ah[r * WSTRIDE + kq * 2] = hi;
                *(uint2*)&Al[r * WSTRIDE + kq * 2] = lo;
            }
            {
                int term = idx >> 9, rem = idx & 511;
                int r = rem >> 2, q = rem & 3;
                uint32_t* dst = term ? Bl : Bh;
                *(uint4*)&dst[r * WSTRIDE + q * 4] = rb[it];
            }
        }
        __syncthreads();

        // ---- prefetch next tile ----
        if (kt + 1 < nk) {
            int k0 = (kt + 1) * KT;
            #pragma unroll
            for (int it = 0; it < 4; ++it) {
                int idx = tid + it * 256;
                {
                    int r = idx >> 3, kq = idx & 7;
                    int gr = row0 + r, gk = k0 + kq * 4;
                    ra[it] = (gr < M && gk < K) ? *(const float4*)(A + (size_t)gr * K + gk)
                                                : make_float4(0.f, 0.f, 0.f, 0.f);
                }
                {
                    int term = idx >> 9, rem = idx & 511;
                    int r = rem >> 2, q = rem & 3;
                    rb[it] = *(const uint4*)((term ? Wl : Wh) +
                             (size_t)(col0 + r) * Kpad + k0 + q * 8);
                }
            }
        }

        // ---- compute: 2 k16-steps x 4 terms x 16 MMAs ----
        #pragma unroll
        for (int ks = 0; ks < 2; ++ks) {
            int p0 = ks * 8;
            uint32_t afh[4][4], afl[4][4], bfh[4][2], bfl[4][2];
            #pragma unroll
            for (int i = 0; i < 4; ++i) {
                int m = wm + i * 16 + g;
                int o0 = m * WSTRIDE + p0 + t;
                int o1 = (m + 8) * WSTRIDE + p0 + t;
                afh[i][0] = Ah[o0];     afh[i][1] = Ah[o1];
                afh[i][2] = Ah[o0 + 4]; afh[i][3] = Ah[o1 + 4];
                afl[i][0] = Al[o0];     afl[i][1] = Al[o1];
                afl[i][2] = Al[o0 + 4]; afl[i][3] = Al[o1 + 4];
            }
            #pragma unroll
            for (int j = 0; j < 4; ++j) {
                int n = wn + j * 8 + g;
                int o = n * WSTRIDE + p0 + t;
                bfh[j][0] = Bh[o]; bfh[j][1] = Bh[o + 4];
                bfl[j][0] = Bl[o]; bfl[j][1] = Bl[o + 4];
            }
            #pragma unroll
            for (int i = 0; i < 4; ++i)
                #pragma unroll
                for (int j = 0; j < 4; ++j) {
                    mma16(c[i][j], afl[i], bfl[j]);   // smallest terms first
                    mma16(c[i][j], afl[i], bfh[j]);
                    mma16(c[i][j], afh[i], bfl[j]);
                    mma16(c[i][j], afh[i], bfh[j]);
                }
        }
        __syncthreads();
    }

    // ---- epilogue: bias + optional relu, float2 stores ----
    #pragma unroll
    for (int i = 0; i < 4; ++i) {
        int r = row0 + wm + i * 16 + g;
        #pragma unroll
        for (int j = 0; j < 4; ++j) {
            int cc = col0 + wn + j * 8 + 2 * t;
            if (cc >= N) continue;
            float bx = bias[cc], by = bias[cc + 1];
            if (r < M) {
                float2 v = make_float2(c[i][j][0] + bx, c[i][j][1] + by);
                if (doRelu) { v.x = fmaxf(v.x, 0.f); v.y = fmaxf(v.y, 0.f); }
                *(float2*)&C[(size_t)r * N + cc] = v;
            }
            int r2 = r + 8;
            if (r2 < M) {
                float2 v = make_float2(c[i][j][2] + bx, c[i][j][3] + by);
                if (doRelu) { v.x = fmaxf(v.x, 0.f); v.y = fmaxf(v.y, 0.f); }
                *(float2*)&C[(size_t)r2 * N + cc] = v;
            }
        }
    }
}

// ---------------- BN pass 1: per-channel sum ----------------
#define BNROWS 256
__global__ void bn_sum_kernel(const float* __restrict__ X) {
    int c = threadIdx.x;
    if (c >= EMB) return;
    int r0 = blockIdx.x * BNROWS;
    int r1 = min(r0 + BNROWS, N_NODES);
    float s = 0.f;
    for (int r = r0; r < r1; ++r) s += X[(size_t)r * EMB + c];
    atomicAdd(&g_stats[c], s);
}

// ---------------- BN pass 2: centered sumsq ----------------
__global__ void bn_sumsq_kernel(const float* __restrict__ X) {
    int c = threadIdx.x;
    if (c >= EMB) return;
    float mu = g_stats[c] * (1.f / N_NODES);
    int r0 = blockIdx.x * BNROWS;
    int r1 = min(r0 + BNROWS, N_NODES);
    float s = 0.f;
    for (int r = r0; r < r1; ++r) {
        float d = X[(size_t)r * EMB + c] - mu;
        s += d * d;
    }
    atomicAdd(&g_stats[EMB + c], s);
}

// ---------------- BN apply (+optional relu) ----------------
__global__ void bn_apply_kernel(const float* __restrict__ X,
                                const float* __restrict__ gamma,
                                const float* __restrict__ beta,
                                int l, int doRelu) {
    int idx = blockIdx.x * blockDim.x + threadIdx.x;
    if (idx >= N_NODES * EMB) return;
    int c = idx % EMB;
    float mu = g_stats[c] * (1.f / N_NODES);
    float var = g_stats[EMB + c] * (1.f / N_NODES);
    float sc = rsqrtf(var + BN_EPS) * gamma[l * EMB + c];
    float v = (X[idx] - mu) * sc + beta[l * EMB + c];
    g_h[idx] = doRelu ? fmaxf(v, 0.f) : v;
}

// ---------------- pooling ----------------
__global__ void pool_zero_kernel(float* __restrict__ out) {
    int idx = blockIdx.x * blockDim.x + threadIdx.x;
    if (idx < NUM_GRAPHS) g_counts[idx] = 0.f;
    if (idx < NUM_GRAPHS * EMB) out[idx] = 0.f;
}
__global__ void pool_count_kernel(const int* __restrict__ batch) {
    int i = blockIdx.x * blockDim.x + threadIdx.x;
    if (i >= N_NODES) return;
    atomicAdd(&g_counts[batch[i]], 1.f);
}
__global__ void pool_scatter_kernel(const int* __restrict__ batch,
                                    float* __restrict__ out) {
    int idx = blockIdx.x * blockDim.x + threadIdx.x;
    if (idx >= N_NODES * EMB) return;
    int i = idx / EMB, c = idx - i * EMB;
    atomicAdd(&out[(size_t)batch[i] * EMB + c], g_h[idx]);
}
__global__ void pool_div_kernel(float* __restrict__ out) {
    int idx = blockIdx.x * blockDim.x + threadIdx.x;
    if (idx >= NUM_GRAPHS * EMB) return;
    out[idx] /= fmaxf(g_counts[idx / EMB], 1.f);
}

// ---------------- launch ----------------
extern "C" void kernel_launch(void* const* d_in, const int* in_sizes, int n_in,
                              void* d_out, int out_size) {
    const int*   x        = (const int*)d_in[0];
    const int*   edge_idx = (const int*)d_in[1];
    const int*   edge_att = (const int*)d_in[2];
    const int*   batch    = (const int*)d_in[3];
    const float* x_emb1   = (const float*)d_in[4];
    const float* x_emb2   = (const float*)d_in[5];
    const float* edge_e1  = (const float*)d_in[6];
    const float* edge_e2  = (const float*)d_in[7];
    const float* W1       = (const float*)d_in[8];
    const float* b1       = (const float*)d_in[9];
    const float* W2       = (const float*)d_in[10];
    const float* b2       = (const float*)d_in[11];
    const float* gamma    = (const float*)d_in[12];
    const float* beta     = (const float*)d_in[13];
    float* out = (float*)d_out;

    const int NE = N_NODES * EMB;
    const int TPB = 256;

    init_h_kernel<<<(NE + TPB - 1) / TPB, TPB>>>(x, x_emb1, x_emb2);

    float *p_agg, *p_t;
    __nv_bfloat16 *p_wh, *p_wl;
    cudaGetSymbolAddress((void**)&p_agg, g_agg);
    cudaGetSymbolAddress((void**)&p_t, g_t);
    cudaGetSymbolAddress((void**)&p_wh, g_wth);
    cudaGetSymbolAddress((void**)&p_wl, g_wtl);

    const int MT = (N_NODES + 127) / 128;   // 782
    // GEMM1: N=600 -> Npad=640, K=300 -> Kpad=320
    // GEMM2: N=300 -> Npad=384, K=600 -> Kpad=640
    dim3 tb(32, 8);
    dim3 tr1(640 / 32, 320 / 32);
    dim3 tr2(384 / 32, 640 / 32);
    dim3 gg1(5, MT), gg2(3, MT);
    int bn_grid = (N_NODES + BNROWS - 1) / BNROWS;

    for (int l = 0; l < NUM_LAYER; ++l) {
        build_tab_kernel<<<(9 * EMB + TPB - 1) / TPB, TPB>>>(edge_e1, edge_e2, l);
        init_agg_kernel<<<(NE + TPB - 1) / TPB, TPB>>>();
        scatter_edges_kernel<<<(N_EDGES + 7) / 8, 256>>>(edge_idx, edge_att);

        // t = relu(agg @ W1[l] + b1[l])   [N, 600]
        transpose_split_kernel<<<tr1, tb>>>(W1 + (size_t)l * EMB * EMB2,
                                            EMB2, EMB, 640, 320);
        gemm_bf16x4_kernel<<<gg1, 256>>>(p_agg, p_wh, p_wl,
                                         b1 + l * EMB2, p_t,
                                         N_NODES, EMB2, EMB, 320, 1);
        // h2 = t @ W2[l] + b2[l]          [N, 300]
        transpose_split_kernel<<<tr2, tb>>>(W2 + (size_t)l * EMB2 * EMB,
                                            EMB, EMB2, 384, 640);
        gemm_bf16x4_kernel<<<gg2, 256>>>(p_t, p_wh, p_wl,
                                         b2 + l * EMB, p_agg,
                                         N_NODES, EMB, EMB2, 640, 0);

        bn_sum_kernel<<<bn_grid, 320>>>(p_agg);
        bn_sumsq_kernel<<<bn_grid, 320>>>(p_agg);
        bn_apply_kernel<<<(NE + TPB - 1) / TPB, TPB>>>(p_agg, gamma, beta, l,
                                                        (l == NUM_LAYER - 1) ? 0 : 1);
    }

    pool_zero_kernel<<<(NUM_GRAPHS * EMB + TPB - 1) / TPB, TPB>>>(out);
    pool_count_kernel<<<(N_NODES + TPB - 1) / TPB, TPB>>>(batch);
    pool_scatter_kernel<<<(NE + TPB - 1) / TPB, TPB>>>(batch, out);
    pool_div_kernel<<<(NUM_GRAPHS * EMB + TPB - 1) / TPB, TPB>>>(out);
}

// round 6
// speedup vs baseline: 3.1641x; 1.1720x over previous
#include <cuda_runtime.h>
#include <cuda_fp16.h>
#include <math.h>
#include <stdint.h>

#define N_NODES   100000
#define N_EDGES   200000
#define EMB       300
#define EMB2      600
#define NUM_LAYER 5
#define NUM_GRAPHS 5000
#define BN_EPS    1e-5f

// ---------------- device scratch (allocation-free) ----------------
__device__ __align__(16) float g_h[N_NODES * EMB];
__device__ __align__(16) float g_agg[N_NODES * EMB];
__device__ __align__(16) float g_t[N_NODES * EMB2];
__device__ __align__(16) float g_tab[9 * EMB];
__device__ float g_stats[2 * EMB];
__device__ float g_counts[NUM_GRAPHS];
// transposed + split weights (fp16 hi/lo), zero-padded: max 384x640 = 245760
__device__ __align__(16) __half g_wth[245760];
__device__ __align__(16) __half g_wtl[245760];

__device__ __forceinline__ uint32_t smem_u32(const void* p) {
    uint32_t a;
    asm("{ .reg .u64 t; cvta.to.shared.u64 t, %1; cvt.u32.u64 %0, t; }" : "=r"(a) : "l"(p));
    return a;
}

// ---------------- h0 = x_emb1[x0] + x_emb2[x1] ----------------
__global__ void init_h_kernel(const int* __restrict__ x,
                              const float* __restrict__ e1,
                              const float* __restrict__ e2) {
    int idx = blockIdx.x * blockDim.x + threadIdx.x;
    if (idx >= N_NODES * EMB) return;
    int i = idx / EMB, c = idx - i * EMB;
    int a = x[2 * i], b = x[2 * i + 1];
    g_h[idx] = e1[a * EMB + c] + e2[b * EMB + c];
}

// ---------------- per-layer eemb table ----------------
__global__ void build_tab_kernel(const float* __restrict__ e1,
                                 const float* __restrict__ e2, int l) {
    int idx = blockIdx.x * blockDim.x + threadIdx.x;
    if (idx >= 9 * EMB) return;
    int t = idx / EMB, c = idx - t * EMB;
    int a = t / 3, b = t - a * 3;
    g_tab[idx] = e1[(l * 6 + a) * EMB + c] + e2[(l * 3 + b) * EMB + c];
}

__global__ void zero_stats_kernel() {
    int idx = blockIdx.x * blockDim.x + threadIdx.x;
    if (idx < 2 * EMB) g_stats[idx] = 0.f;
}

// ---------------- agg = h + tab[0]  (first layer only) ----------------
__global__ void init_agg_kernel() {
    int idx = blockIdx.x * blockDim.x + threadIdx.x;
    if (idx >= N_NODES * EMB) return;
    g_agg[idx] = g_h[idx] + g_tab[idx % EMB];
}

// ---------------- edge scatter: agg[dst] += h[src] + tab[attr] ----------------
__global__ __launch_bounds__(256) void scatter_edges_kernel(
        const int* __restrict__ ei, const int* __restrict__ ea) {
    int e = blockIdx.x * 8 + (threadIdx.x >> 5);
    if (e >= N_EDGES) return;
    int lane = threadIdx.x & 31;
    int src = ei[e];
    int dst = ei[N_EDGES + e];
    int t = ea[2 * e] * 3 + ea[2 * e + 1];
    const float4* hs = (const float4*)(g_h + (size_t)src * EMB);
    const float4* tb = (const float4*)(g_tab + t * EMB);
    float* ag = g_agg + (size_t)dst * EMB;
    #pragma unroll
    for (int i = lane; i < EMB / 4; i += 32) {
        float4 hv = hs[i];
        float4 tv = tb[i];
        atomicAdd(&ag[4 * i + 0], hv.x + tv.x);
        atomicAdd(&ag[4 * i + 1], hv.y + tv.y);
        atomicAdd(&ag[4 * i + 2], hv.z + tv.z);
        atomicAdd(&ag[4 * i + 3], hv.w + tv.w);
    }
}

// ---------------- weight transpose + fp16 hi/lo split ----------------
// W [K,N] fp32  ->  g_wth/g_wtl [Npad, Kpad] fp16, zero-padded.
__global__ void transpose_split_kernel(const float* __restrict__ W,
                                       int N, int K, int Npad, int Kpad) {
    __shared__ float tile[32][33];
    int tx = threadIdx.x, ty = threadIdx.y;
    int nb = blockIdx.x * 32, kb = blockIdx.y * 32;
    #pragma unroll
    for (int j = 0; j < 4; ++j) {
        int gk = kb + ty + j * 8, gn = nb + tx;
        tile[ty + j * 8][tx] = (gk < K && gn < N) ? W[(size_t)gk * N + gn] : 0.f;
    }
    __syncthreads();
    #pragma unroll
    for (int j = 0; j < 4; ++j) {
        int gn = nb + ty + j * 8, gk = kb + tx;
        if (gn < Npad && gk < Kpad) {
            float v = tile[tx][ty + j * 8];
            __half hi = __float2half_rn(v);
            __half lo = __float2half_rn(v - __half2float(hi));
            g_wth[(size_t)gn * Kpad + gk] = hi;
            g_wtl[(size_t)gn * Kpad + gk] = lo;
        }
    }
}

// ====== 3-term split-fp16 tensor GEMM: C = act(A@W + bias) ======
// Block 128x128, K-tile 32, 8 warps x (64x32), mma.m16n8k16.f16, ldmatrix loads.
// D = Al*Bh + Ah*Bl + Ah*Bh (fp32 accumulate); Al*Bl ~ 2^-22, dropped.
#define KT 32
#define WSTRIDE 20   // words per smem row (16 data + 4 pad) = 80 B

__device__ __forceinline__ void mma16f(float* c, const uint32_t* a, const uint32_t* b) {
    asm volatile(
        "mma.sync.aligned.m16n8k16.row.col.f32.f16.f16.f32 "
        "{%0,%1,%2,%3},{%4,%5,%6,%7},{%8,%9},{%0,%1,%2,%3};\n"
        : "+f"(c[0]), "+f"(c[1]), "+f"(c[2]), "+f"(c[3])
        : "r"(a[0]), "r"(a[1]), "r"(a[2]), "r"(a[3]), "r"(b[0]), "r"(b[1]));
}
__device__ __forceinline__ void ldmx4(uint32_t* r, uint32_t addr) {
    asm volatile("ldmatrix.sync.aligned.m8n8.x4.shared.b16 {%0,%1,%2,%3}, [%4];"
        : "=r"(r[0]), "=r"(r[1]), "=r"(r[2]), "=r"(r[3]) : "r"(addr));
}

__device__ __forceinline__ void split4h(float4 f, uint2& hi, uint2& lo) {
    __half h0 = __float2half_rn(f.x), h1 = __float2half_rn(f.y),
           h2 = __float2half_rn(f.z), h3 = __float2half_rn(f.w);
    __half l0 = __float2half_rn(f.x - __half2float(h0)),
           l1 = __float2half_rn(f.y - __half2float(h1)),
           l2 = __float2half_rn(f.z - __half2float(h2)),
           l3 = __float2half_rn(f.w - __half2float(h3));
    __half2 ha = __halves2half2(h0, h1), hb = __halves2half2(h2, h3);
    __half2 la = __halves2half2(l0, l1), lb = __halves2half2(l2, l3);
    hi = make_uint2(*(uint32_t*)&ha, *(uint32_t*)&hb);
    lo = make_uint2(*(uint32_t*)&la, *(uint32_t*)&lb);
}

__global__ __launch_bounds__(256) void gemm_fp16x3_kernel(
        const float* __restrict__ A,
        const __half* __restrict__ Wh,
        const __half* __restrict__ Wl,
        const float* __restrict__ bias, float* __restrict__ C,
        int M, int N, int K, int Kpad, int doRelu) {
    __shared__ __align__(16) uint32_t Ah[128 * WSTRIDE];
    __shared__ __align__(16) uint32_t Al[128 * WSTRIDE];
    __shared__ __align__(16) uint32_t Bh[128 * WSTRIDE];
    __shared__ __align__(16) uint32_t Bl[128 * WSTRIDE];

    const int tid  = threadIdx.x;
    const int lane = tid & 31;
    const int warp = tid >> 5;
    const int g = lane >> 2;
    const int t = lane & 3;
    const int wm = (warp & 1) * 64;
    const int wn = (warp >> 1) * 32;
    const int row0 = blockIdx.y * 128;
    const int col0 = blockIdx.x * 128;

    const uint32_t sAh = smem_u32(Ah), sAl = smem_u32(Al);
    const uint32_t sBh = smem_u32(Bh), sBl = smem_u32(Bl);

    // ldmatrix lane selectors (byte addresses; rows are 80 B apart)
    const int l8  = lane & 7;
    const int sel = lane >> 3;
    const int a_row  = l8 + ((sel & 1) << 3);       // +8 rows for matrices 1,3
    const int a_koff = ((sel >> 1) << 3) * 2;       // +8 halfs (16 B) for matrices 2,3
    const int b_row  = l8 + ((sel >> 1) << 3);      // +8 n-rows for matrices 2,3
    const int b_koff = ((sel & 1) << 3) * 2;        // +8 halfs for matrices 1,3

    float c[4][4][4] = {};
    float4 ra[4];
    uint4  rb[4];

    const int nk = (K + KT - 1) / KT;

    // ---- prefetch tile 0 ----
    #pragma unroll
    for (int it = 0; it < 4; ++it) {
        int idx = tid + it * 256;
        {
            int r = idx >> 3, kq = idx & 7;
            int gr = row0 + r, gk = kq * 4;
            ra[it] = (gr < M && gk < K) ? *(const float4*)(A + (size_t)gr * K + gk)
                                        : make_float4(0.f, 0.f, 0.f, 0.f);
        }
        {
            int term = idx >> 9, rem = idx & 511;
            int r = rem >> 2, q = rem & 3;
            rb[it] = *(const uint4*)((term ? Wl : Wh) + (size_t)(col0 + r) * Kpad + q * 8);
        }
    }

    for (int kt = 0; kt < nk; ++kt) {
        // ---- store staged tile to smem ----
        #pragma unroll
        for (int it = 0; it < 4; ++it) {
            int idx = tid + it * 256;
            {
                int r = idx >> 3, kq = idx & 7;
                uint2 hi, lo;
                split4h(ra[it], hi, lo);
                *(uint2*)&Ah[r * WSTRIDE + kq * 2] = hi;
                *(uint2*)&Al[r * WSTRIDE + kq * 2] = lo;
            }
            {
                int term = idx >> 9, rem = idx & 511;
                int r = rem >> 2, q = rem & 3;
                uint32_t* dst = term ? Bl : Bh;
                *(uint4*)&dst[r * WSTRIDE + q * 4] = rb[it];
            }
        }
        __syncthreads();

        // ---- prefetch next tile ----
        if (kt + 1 < nk) {
            int k0 = (kt + 1) * KT;
            #pragma unroll
            for (int it = 0; it < 4; ++it) {
                int idx = tid + it * 256;
                {
                    int r = idx >> 3, kq = idx & 7;
                    int gr = row0 + r, gk = k0 + kq * 4;
                    ra[it] = (gr < M && gk < K) ? *(const float4*)(A + (size_t)gr * K + gk)
                                                : make_float4(0.f, 0.f, 0.f, 0.f);
                }
                {
                    int term = idx >> 9, rem = idx & 511;
                    int r = rem >> 2, q = rem & 3;
                    rb[it] = *(const uint4*)((term ? Wl : Wh) +
                             (size_t)(col0 + r) * Kpad + k0 + q * 8);
                }
            }
        }

        // ---- compute: 2 k16-steps, ldmatrix + 48 MMAs each ----
        #pragma unroll
        for (int ks = 0; ks < 2; ++ks) {
            const int kb = ks * 32 + b_koff;   // byte offset of k within row (16 halfs/ks)
            const int ka = ks * 32 + a_koff;
            uint32_t afh[4][4], afl[4][4], bfh[4][2], bfl[4][2];
            #pragma unroll
            for (int i = 0; i < 4; ++i) {
                uint32_t ro = (uint32_t)(wm + i * 16 + a_row) * 80 + ka;
                ldmx4(afh[i], sAh + ro);
                ldmx4(afl[i], sAl + ro);
            }
            #pragma unroll
            for (int j2 = 0; j2 < 2; ++j2) {
                uint32_t ro = (uint32_t)(wn + j2 * 16 + b_row) * 80 + kb;
                uint32_t r[4];
                ldmx4(r, sBh + ro);
                bfh[2 * j2][0] = r[0]; bfh[2 * j2][1] = r[1];
                bfh[2 * j2 + 1][0] = r[2]; bfh[2 * j2 + 1][1] = r[3];
                ldmx4(r, sBl + ro);
                bfl[2 * j2][0] = r[0]; bfl[2 * j2][1] = r[1];
                bfl[2 * j2 + 1][0] = r[2]; bfl[2 * j2 + 1][1] = r[3];
            }
            #pragma unroll
            for (int i = 0; i < 4; ++i)
                #pragma unroll
                for (int j = 0; j < 4; ++j) {
                    mma16f(c[i][j], afl[i], bfh[j]);
                    mma16f(c[i][j], afh[i], bfl[j]);
                    mma16f(c[i][j], afh[i], bfh[j]);
                }
        }
        __syncthreads();
    }

    // ---- epilogue: bias + optional relu, float2 stores ----
    #pragma unroll
    for (int i = 0; i < 4; ++i) {
        int r = row0 + wm + i * 16 + g;
        #pragma unroll
        for (int j = 0; j < 4; ++j) {
            int cc = col0 + wn + j * 8 + 2 * t;
            if (cc >= N) continue;
            float bx = bias[cc], by = bias[cc + 1];
            if (r < M) {
                float2 v = make_float2(c[i][j][0] + bx, c[i][j][1] + by);
                if (doRelu) { v.x = fmaxf(v.x, 0.f); v.y = fmaxf(v.y, 0.f); }
                *(float2*)&C[(size_t)r * N + cc] = v;
            }
            int r2 = r + 8;
            if (r2 < M) {
                float2 v = make_float2(c[i][j][2] + bx, c[i][j][3] + by);
                if (doRelu) { v.x = fmaxf(v.x, 0.f); v.y = fmaxf(v.y, 0.f); }
                *(float2*)&C[(size_t)r2 * N + cc] = v;
            }
        }
    }
}

// ---------------- BN pass 1: per-channel sum ----------------
#define BNROWS 256
__global__ void bn_sum_kernel(const float* __restrict__ X) {
    int c = threadIdx.x;
    if (c >= EMB) return;
    int r0 = blockIdx.x * BNROWS;
    int r1 = min(r0 + BNROWS, N_NODES);
    float s = 0.f;
    for (int r = r0; r < r1; ++r) s += X[(size_t)r * EMB + c];
    atomicAdd(&g_stats[c], s);
}

// ---------------- BN pass 2: centered sumsq ----------------
__global__ void bn_sumsq_kernel(const float* __restrict__ X) {
    int c = threadIdx.x;
    if (c >= EMB) return;
    float mu = g_stats[c] * (1.f / N_NODES);
    int r0 = blockIdx.x * BNROWS;
    int r1 = min(r0 + BNROWS, N_NODES);
    float s = 0.f;
    for (int r = r0; r < r1; ++r) {
        float d = X[(size_t)r * EMB + c] - mu;
        s += d * d;
    }
    atomicAdd(&g_stats[EMB + c], s);
}

// ---------------- BN apply; optionally fused with next-layer agg init ----------------
// doRelu: apply relu to h. doAgg: also write g_agg = h + g_tab[0:EMB] (next layer).
__global__ void bn_apply_kernel(const float* __restrict__ X,
                                const float* __restrict__ gamma,
                                const float* __restrict__ beta,
                                int l, int doRelu, int doAgg) {
    int idx = blockIdx.x * blockDim.x + threadIdx.x;
    if (idx >= N_NODES * EMB) return;
    int c = idx % EMB;
    float mu = g_stats[c] * (1.f / N_NODES);
    float var = g_stats[EMB + c] * (1.f / N_NODES);
    float sc = rsqrtf(var + BN_EPS) * gamma[l * EMB + c];
    float v = (X[idx] - mu) * sc + beta[l * EMB + c];
    if (doRelu) v = fmaxf(v, 0.f);
    g_h[idx] = v;
    if (doAgg) g_agg[idx] = v + g_tab[c];
}

// ---------------- pooling ----------------
__global__ void pool_zero_kernel(float* __restrict__ out) {
    int idx = blockIdx.x * blockDim.x + threadIdx.x;
    if (idx < NUM_GRAPHS) g_counts[idx] = 0.f;
    if (idx < NUM_GRAPHS * EMB) out[idx] = 0.f;
}
__global__ void pool_count_kernel(const int* __restrict__ batch) {
    int i = blockIdx.x * blockDim.x + threadIdx.x;
    if (i >= N_NODES) return;
    atomicAdd(&g_counts[batch[i]], 1.f);
}
__global__ void pool_scatter_kernel(const int* __restrict__ batch,
                                    float* __restrict__ out) {
    int idx = blockIdx.x * blockDim.x + threadIdx.x;
    if (idx >= N_NODES * EMB) return;
    int i = idx / EMB, c = idx - i * EMB;
    atomicAdd(&out[(size_t)batch[i] * EMB + c], g_h[idx]);
}
__global__ void pool_div_kernel(float* __restrict__ out) {
    int idx = blockIdx.x * blockDim.x + threadIdx.x;
    if (idx >= NUM_GRAPHS * EMB) return;
    out[idx] /= fmaxf(g_counts[idx / EMB], 1.f);
}

// ---------------- launch ----------------
extern "C" void kernel_launch(void* const* d_in, const int* in_sizes, int n_in,
                              void* d_out, int out_size) {
    const int*   x        = (const int*)d_in[0];
    const int*   edge_idx = (const int*)d_in[1];
    const int*   edge_att = (const int*)d_in[2];
    const int*   batch    = (const int*)d_in[3];
    const float* x_emb1   = (const float*)d_in[4];
    const float* x_emb2   = (const float*)d_in[5];
    const float* edge_e1  = (const float*)d_in[6];
    const float* edge_e2  = (const float*)d_in[7];
    const float* W1       = (const float*)d_in[8];
    const float* b1       = (const float*)d_in[9];
    const float* W2       = (const float*)d_in[10];
    const float* b2       = (const float*)d_in[11];
    const float* gamma    = (const float*)d_in[12];
    const float* beta     = (const float*)d_in[13];
    float* out = (float*)d_out;

    const int NE = N_NODES * EMB;
    const int TPB = 256;

    init_h_kernel<<<(NE + TPB - 1) / TPB, TPB>>>(x, x_emb1, x_emb2);

    float *p_agg, *p_t;
    __half *p_wh, *p_wl;
    cudaGetSymbolAddress((void**)&p_agg, g_agg);
    cudaGetSymbolAddress((void**)&p_t, g_t);
    cudaGetSymbolAddress((void**)&p_wh, g_wth);
    cudaGetSymbolAddress((void**)&p_wl, g_wtl);

    const int MT = (N_NODES + 127) / 128;   // 782
    dim3 tb(32, 8);
    dim3 tr1(640 / 32, 320 / 32);   // GEMM1 weights: Npad=640, Kpad=320
    dim3 tr2(384 / 32, 640 / 32);   // GEMM2 weights: Npad=384, Kpad=640
    dim3 gg1(5, MT), gg2(3, MT);
    int bn_grid = (N_NODES + BNROWS - 1) / BNROWS;

    // layer-0 aggregation init
    build_tab_kernel<<<(9 * EMB + TPB - 1) / TPB, TPB>>>(edge_e1, edge_e2, 0);
    init_agg_kernel<<<(NE + TPB - 1) / TPB, TPB>>>();

    for (int l = 0; l < NUM_LAYER; ++l) {
        zero_stats_kernel<<<3, 256>>>();
        scatter_edges_kernel<<<(N_EDGES + 7) / 8, 256>>>(edge_idx, edge_att);

        // t = relu(agg @ W1[l] + b1[l])   [N, 600]
        transpose_split_kernel<<<tr1, tb>>>(W1 + (size_t)l * EMB * EMB2,
                                            EMB2, EMB, 640, 320);
        gemm_fp16x3_kernel<<<gg1, 256>>>(p_agg, p_wh, p_wl,
                                         b1 + l * EMB2, p_t,
                                         N_NODES, EMB2, EMB, 320, 1);
        // h2 = t @ W2[l] + b2[l]          [N, 300]
        transpose_split_kernel<<<tr2, tb>>>(W2 + (size_t)l * EMB2 * EMB,
                                            EMB, EMB2, 384, 640);
        gemm_fp16x3_kernel<<<gg2, 256>>>(p_t, p_wh, p_wl,
                                         b2 + l * EMB, p_agg,
                                         N_NODES, EMB, EMB2, 640, 0);

        bn_sum_kernel<<<bn_grid, 320>>>(p_agg);
        bn_sumsq_kernel<<<bn_grid, 320>>>(p_agg);

        int last = (l == NUM_LAYER - 1);
        if (!last) {
            // build next layer's table BEFORE the fused apply+agg
            build_tab_kernel<<<(9 * EMB + TPB - 1) / TPB, TPB>>>(edge_e1, edge_e2, l + 1);
            bn_apply_kernel<<<(NE + TPB - 1) / TPB, TPB>>>(p_agg, gamma, beta, l, 1, 1);
        } else {
            bn_apply_kernel<<<(NE + TPB - 1) / TPB, TPB>>>(p_agg, gamma, beta, l, 0, 0);
        }
    }

    pool_zero_kernel<<<(NUM_GRAPHS * EMB + TPB - 1) / TPB, TPB>>>(out);
    pool_count_kernel<<<(N_NODES + TPB - 1) / TPB, TPB>>>(batch);
    pool_scatter_kernel<<<(NE + TPB - 1) / TPB, TPB>>>(batch, out);
    pool_div_kernel<<<(NUM_GRAPHS * EMB + TPB - 1) / TPB, TPB>>>(out);
}